// round 9
// baseline (speedup 1.0000x reference)
#include <cuda_runtime.h>
#include <cuda_bf16.h>
#include <mma.h>
#include <cstdint>

using namespace nvcuda;

#define N_ROWS 131072
#define DIM    256
#define KCB    1024
#define DELTA  1.25e-3f

// rescue tile
#define BM 32
#define BN 128
#define BD 32
#define PAD 4

__device__ float  g_cnorm[KCB];
__device__ float  g_zn[N_ROWS];
__device__ int    g_ids[N_ROWS];
__device__ int    g_flagged[N_ROWS];
__device__ int    g_nflag;
__device__ double g_loss;
__device__ __align__(16) __nv_bfloat16 g_cbh[KCB * DIM];   // pre-converted codebook

typedef unsigned long long u64;

#define FMA_F32X2(d, a, b, c) \
    asm("fma.rn.f32x2 %0, %1, %2, %3;" : "=l"(d) : "l"(a), "l"(b), "l"(c))
#define DUP_F32X2(d, x) \
    asm("mov.b64 %0, {%1, %1};" : "=l"(d) : "r"(x))
__device__ __forceinline__ float lo32(u64 v) { return __uint_as_float((unsigned)(v & 0xFFFFFFFFu)); }
__device__ __forceinline__ float hi32(u64 v) { return __uint_as_float((unsigned)(v >> 32)); }

// ---------------------------------------------------------------------------
// Bit-exact row norms (XLA order) + codebook bf16 pre-conversion
// ---------------------------------------------------------------------------
__device__ __forceinline__ float row_sumsq_warp(const float* __restrict__ row, int lane) {
    float s = 0.f;
#pragma unroll
    for (int i = 0; i < DIM / 32; ++i) {
        float v = row[lane + i * 32];
        s = __fadd_rn(s, __fmul_rn(v, v));
    }
#pragma unroll
    for (int o = 16; o > 0; o >>= 1)
        s = __fadd_rn(s, __shfl_down_sync(0xFFFFFFFFu, s, o));
    return s;
}

__global__ void norms_kernel(const float* __restrict__ z, const float* __restrict__ cb) {
    int gtid = blockIdx.x * blockDim.x + threadIdx.x;
    int warp = gtid >> 5;
    int lane = threadIdx.x & 31;
    if (gtid == 0) { g_loss = 0.0; g_nflag = 0; }
    // convert codebook to bf16 (8 elements per thread)
    if (gtid < KCB * DIM / 8) {
        const float4* p = (const float4*)&cb[(size_t)gtid * 8];
        float4 a = p[0], b = p[1];
        __nv_bfloat162 h0 = __floats2bfloat162_rn(a.x, a.y), h1 = __floats2bfloat162_rn(a.z, a.w);
        __nv_bfloat162 h2 = __floats2bfloat162_rn(b.x, b.y), h3 = __floats2bfloat162_rn(b.z, b.w);
        uint4 u;
        u.x = *(uint32_t*)&h0; u.y = *(uint32_t*)&h1;
        u.z = *(uint32_t*)&h2; u.w = *(uint32_t*)&h3;
        *(uint4*)&g_cbh[(size_t)gtid * 8] = u;
    }
    if (warp < N_ROWS) {
        float s = row_sumsq_warp(z + (size_t)warp * DIM, lane);
        if (lane == 0) g_zn[warp] = s;
    }
    if (warp < KCB) {
        float s = row_sumsq_warp(cb + (size_t)warp * DIM, lane);
        if (lane == 0) g_cnorm[warp] = s;
    }
}

// ---------------------------------------------------------------------------
// Screening: wmma bf16 GEMM + per-row top-2.
// CTA = 256 threads (8 warps), 256 rows/CTA; warp w owns rows 32w..32w+31
// (2 fa tiles). ns processed in 2 passes of 4 (caps acc regs at 64).
// ---------------------------------------------------------------------------
#define LDZ 264
#define S_Z    0                       // z bf16 [256][LDZ]      135168 B
#define S_CB   135168                  // cb bf16 [128][LDZ]      67584 B
#define S_CN   202752                  // cnorm f32 [1024]         4096 B
#define S_SCR  206848                  // scratch f32 [8][16][20] 10240 B
#define S_TOT  217088

__global__ void __launch_bounds__(256)
screen_kernel(const float* __restrict__ z) {
    extern __shared__ char smem[];
    __nv_bfloat16* zt  = (__nv_bfloat16*)(smem + S_Z);
    __nv_bfloat16* cbt = (__nv_bfloat16*)(smem + S_CB);
    float* cn_s = (float*)(smem + S_CN);

    const int tid = threadIdx.x, w = tid >> 5, lane = tid & 31;
    const int blockRow = blockIdx.x * 256;
    float (*scr)[20] = (float(*)[20])(smem + S_SCR + w * 16 * 20 * 4);

    for (int t = tid; t < KCB; t += 256) cn_s[t] = g_cnorm[t];

    // stage z tile [256 x 256] f32 -> bf16 smem
    for (int t = tid; t < 256 * 32; t += 256) {
        int row = t >> 5, c8 = t & 31;
        const float4* p = (const float4*)&z[(size_t)(blockRow + row) * DIM + c8 * 8];
        float4 a = p[0], b = p[1];
        __nv_bfloat162 h0 = __floats2bfloat162_rn(a.x, a.y), h1 = __floats2bfloat162_rn(a.z, a.w);
        __nv_bfloat162 h2 = __floats2bfloat162_rn(b.x, b.y), h3 = __floats2bfloat162_rn(b.z, b.w);
        uint4 u;
        u.x = *(uint32_t*)&h0; u.y = *(uint32_t*)&h1;
        u.z = *(uint32_t*)&h2; u.w = *(uint32_t*)&h3;
        *(uint4*)&zt[row * LDZ + c8 * 8] = u;
    }

    float best[2]  = {3.4e38f, 3.4e38f};
    float best2[2] = {3.4e38f, 3.4e38f};
    int   bidx[2]  = {0, 0};

#pragma unroll 1
    for (int c = 0; c < 8; ++c) {
        __syncthreads();
        // stage pre-converted bf16 codebook chunk [128 x 256]
        for (int t = tid; t < 128 * 32; t += 256) {
            int row = t >> 5, c8 = t & 31;
            uint4 u = *(const uint4*)&g_cbh[(size_t)(c * 128 + row) * DIM + c8 * 8];
            *(uint4*)&cbt[row * LDZ + c8 * 8] = u;
        }
        __syncthreads();

#pragma unroll 1
        for (int pass = 0; pass < 2; ++pass) {
            wmma::fragment<wmma::accumulator, 16, 16, 16, float> facc[2][4];
#pragma unroll
            for (int t = 0; t < 2; ++t)
#pragma unroll
                for (int n = 0; n < 4; ++n) wmma::fill_fragment(facc[t][n], 0.0f);

#pragma unroll 1
            for (int ks = 0; ks < 16; ++ks) {
                wmma::fragment<wmma::matrix_a, 16, 16, 16, __nv_bfloat16, wmma::row_major> fa0, fa1;
                wmma::load_matrix_sync(fa0, zt + (32 * w) * LDZ + 16 * ks, LDZ);
                wmma::load_matrix_sync(fa1, zt + (32 * w + 16) * LDZ + 16 * ks, LDZ);
#pragma unroll
                for (int n = 0; n < 4; ++n) {
                    wmma::fragment<wmma::matrix_b, 16, 16, 16, __nv_bfloat16, wmma::col_major> fb;
                    wmma::load_matrix_sync(fb, cbt + (16 * (pass * 4 + n)) * LDZ + 16 * ks, LDZ);
                    wmma::mma_sync(facc[0][n], fa0, fb, facc[0][n]);
                    wmma::mma_sync(facc[1][n], fa1, fb, facc[1][n]);
                }
            }

            // epilogue: k ascending per row (n ascending); tiles are different rows.
#pragma unroll 1
            for (int n = 0; n < 4; ++n) {
#pragma unroll
                for (int t = 0; t < 2; ++t) {
                    wmma::store_matrix_sync(&scr[0][0], facc[t][n], 20, wmma::mem_row_major);
                    __syncwarp();
                    if (lane < 16) {
#pragma unroll
                        for (int j = 0; j < 16; ++j) {
                            int k = c * 128 + (pass * 4 + n) * 16 + j;
                            float v = fmaf(-2.f, scr[lane][j], cn_s[k]);
                            if (v < best[t]) { best2[t] = best[t]; best[t] = v; bidx[t] = k; }
                            else if (v < best2[t]) best2[t] = v;
                        }
                    }
                    __syncwarp();
                }
            }
        }
    }

    if (lane < 16) {
#pragma unroll
        for (int t = 0; t < 2; ++t) {
            int row = blockRow + w * 32 + t * 16 + lane;
            g_ids[row] = bidx[t];
            if (best2[t] - best[t] < DELTA) {
                int p = atomicAdd(&g_nflag, 1);
                g_flagged[p] = row;
            }
        }
    }
}

// ---------------------------------------------------------------------------
// Exact rescue (bit-exact FFMA2), BM=32 rows/block for low per-block latency.
// 256 thr: tx=tid&15 (8 codes stride 16), ty=tid>>4 owns row pair (2ty,2ty+1).
// ---------------------------------------------------------------------------
__global__ void __launch_bounds__(256)
rescue_kernel(const float* __restrict__ z, const float* __restrict__ cb) {
    __shared__ __align__(16) float zs[BD][BM + PAD];
    __shared__ __align__(16) float cs[BD][BN + PAD];
    __shared__ float zn_s[BM];
    __shared__ int   ridx_s[BM];
    __shared__ float redv[BM][16];
    __shared__ int   redi[BM][16];

    const int nf = g_nflag;
    const int blockRow = blockIdx.x * BM;
    if (blockRow >= nf) return;

    const int tid = threadIdx.x;
    const int tx = tid & 15;
    const int ty = tid >> 4;

    if (tid < BM) {
        int s = blockRow + tid;
        int r = g_flagged[(s < nf) ? s : blockRow];
        ridx_s[tid] = r;
        zn_s[tid] = g_zn[r];
    }

    float bestv[2] = {3.4e38f, 3.4e38f};
    int   besti[2] = {0, 0};

    const int c4 = tid & 7;
    const int r0 = tid >> 3;

#pragma unroll 1
    for (int kt = 0; kt < KCB; kt += BN) {
        u64 acc[8];
#pragma unroll
        for (int j = 0; j < 8; ++j) acc[j] = 0ull;

#pragma unroll 1
        for (int dt = 0; dt < DIM; dt += BD) {
            __syncthreads();
            if (r0 < 32) {  // z tile: 32 rows x 32 d, one float4 per thread
                float4 v = *(const float4*)&z[(size_t)ridx_s[r0] * DIM + dt + c4 * 4];
                zs[c4 * 4 + 0][r0] = v.x; zs[c4 * 4 + 1][r0] = v.y;
                zs[c4 * 4 + 2][r0] = v.z; zs[c4 * 4 + 3][r0] = v.w;
            }
#pragma unroll
            for (int q = 0; q < 4; ++q) {
                int r = q * 32 + r0;
                float4 wv = *(const float4*)&cb[(size_t)(kt + r) * DIM + dt + c4 * 4];
                cs[c4 * 4 + 0][r] = wv.x; cs[c4 * 4 + 1][r] = wv.y;
                cs[c4 * 4 + 2][r] = wv.z; cs[c4 * 4 + 3][r] = wv.w;
            }
            __syncthreads();

#pragma unroll 8
            for (int d = 0; d < BD; ++d) {
                u64 zap = *(const u64*)&zs[d][ty * 2];
#pragma unroll
                for (int j = 0; j < 8; ++j) {
                    float cc = cs[d][tx + 16 * j];
                    u64 cd;
                    DUP_F32X2(cd, __float_as_uint(cc));
                    FMA_F32X2(acc[j], zap, cd, acc[j]);
                }
            }
        }

#pragma unroll
        for (int j = 0; j < 8; ++j) {
            int kk = kt + tx + 16 * j;
            float cn = g_cnorm[kk];
            float a0 = lo32(acc[j]), a1 = hi32(acc[j]);
            float s0 = fmaf(-2.f, a0, zn_s[ty * 2 + 0]);
            float v0 = __fadd_rn(s0, cn);
            if (v0 < bestv[0]) { bestv[0] = v0; besti[0] = kk; }
            float s1 = fmaf(-2.f, a1, zn_s[ty * 2 + 1]);
            float v1 = __fadd_rn(s1, cn);
            if (v1 < bestv[1]) { bestv[1] = v1; besti[1] = kk; }
        }
    }

    __syncthreads();
#pragma unroll
    for (int i = 0; i < 2; ++i) {
        redv[ty * 2 + i][tx] = bestv[i];
        redi[ty * 2 + i][tx] = besti[i];
    }
    __syncthreads();
    if (tid < BM && blockRow + tid < nf) {
        float bv = redv[tid][0];
        int   bi = redi[tid][0];
#pragma unroll
        for (int t = 1; t < 16; ++t) {
            float v = redv[tid][t];
            int   ii = redi[tid][t];
            if (v < bv || (v == bv && ii < bi)) { bv = v; bi = ii; }
        }
        g_ids[ridx_s[tid]] = bi;
    }
}

// ---------------------------------------------------------------------------
// Outputs: z | z_q_st = z + (z_q - z) | ids | loss
// ---------------------------------------------------------------------------
__global__ void output_kernel(const float* __restrict__ z,
                              const float* __restrict__ cb,
                              float* __restrict__ out) {
    const size_t ND = (size_t)N_ROWS * DIM;
    int gtid = blockIdx.x * blockDim.x + threadIdx.x;
    size_t base = (size_t)gtid * 4;

    float local = 0.f;
    if (base < ND) {
        int n = (int)(base / DIM);
        int d = (int)(base % DIM);
        float4 zv = *(const float4*)&z[base];
        int id = g_ids[n];
        float4 cv = *(const float4*)&cb[(size_t)id * DIM + d];
        *(float4*)&out[base] = zv;
        float tx_ = __fadd_rn(cv.x, -zv.x), ty_ = __fadd_rn(cv.y, -zv.y);
        float tz_ = __fadd_rn(cv.z, -zv.z), tw_ = __fadd_rn(cv.w, -zv.w);
        float4 st;
        st.x = __fadd_rn(zv.x, tx_); st.y = __fadd_rn(zv.y, ty_);
        st.z = __fadd_rn(zv.z, tz_); st.w = __fadd_rn(zv.w, tw_);
        *(float4*)&out[ND + base] = st;
        local = tx_ * tx_ + ty_ * ty_ + tz_ * tz_ + tw_ * tw_;
    }
    if (gtid < N_ROWS) out[2 * ND + gtid] = (float)g_ids[gtid];

    __shared__ float warp_s[8];
#pragma unroll
    for (int o = 16; o > 0; o >>= 1)
        local += __shfl_down_sync(0xFFFFFFFFu, local, o);
    if ((threadIdx.x & 31) == 0) warp_s[threadIdx.x >> 5] = local;
    __syncthreads();
    if (threadIdx.x < 8) {
        float v = warp_s[threadIdx.x];
#pragma unroll
        for (int o = 4; o > 0; o >>= 1)
            v += __shfl_down_sync(0xFFu, v, o);
        if (threadIdx.x == 0 && v != 0.f) atomicAdd(&g_loss, (double)v);
    }
}

__global__ void finalize_kernel(float* __restrict__ out) {
    const size_t ND = (size_t)N_ROWS * DIM;
    out[2 * ND + N_ROWS] = (float)(1.25 * g_loss / (double)ND);
}

// ---------------------------------------------------------------------------
extern "C" void kernel_launch(void* const* d_in, const int* in_sizes, int n_in,
                              void* d_out, int out_size) {
    const float* z  = (const float*)d_in[0];
    const float* cb = (const float*)d_in[1];
    float* out = (float*)d_out;

    cudaFuncSetAttribute(screen_kernel, cudaFuncAttributeMaxDynamicSharedMemorySize, S_TOT);

    norms_kernel<<<(N_ROWS * 32 + 255) / 256, 256>>>(z, cb);
    screen_kernel<<<N_ROWS / 256, 256, S_TOT>>>(z);
    rescue_kernel<<<N_ROWS / BM, 256>>>(z, cb);
    const size_t ND = (size_t)N_ROWS * DIM;
    int nblk = (int)((ND / 4 + 255) / 256);
    output_kernel<<<nblk, 256>>>(z, cb, out);
    finalize_kernel<<<1, 1>>>(out);
}

// round 11
// speedup vs baseline: 1.5368x; 1.5368x over previous
#include <cuda_runtime.h>
#include <cuda_bf16.h>
#include <cstdint>

#define N_ROWS 131072
#define DIM    256
#define KCB    1024
#define DELTA  1.0e-3f

// rescue tile
#define BM 32
#define BN 128
#define BD 32
#define PAD 4

__device__ float  g_cnorm[KCB];
__device__ float  g_zn[N_ROWS];
__device__ int    g_ids[N_ROWS];
__device__ int    g_flagged[N_ROWS];
__device__ int    g_nflag;
__device__ double g_loss;
__device__ __align__(16) __nv_bfloat16 g_cbh[KCB * DIM];

typedef unsigned long long u64;

#define FMA_F32X2(d, a, b, c) \
    asm("fma.rn.f32x2 %0, %1, %2, %3;" : "=l"(d) : "l"(a), "l"(b), "l"(c))
#define DUP_F32X2(d, x) \
    asm("mov.b64 %0, {%1, %1};" : "=l"(d) : "r"(x))
__device__ __forceinline__ float lo32(u64 v) { return __uint_as_float((unsigned)(v & 0xFFFFFFFFu)); }
__device__ __forceinline__ float hi32(u64 v) { return __uint_as_float((unsigned)(v >> 32)); }

// ---------------------------------------------------------------------------
// Bit-exact row norms (XLA order) + codebook bf16 pre-conversion
// ---------------------------------------------------------------------------
__device__ __forceinline__ float row_sumsq_warp(const float* __restrict__ row, int lane) {
    float s = 0.f;
#pragma unroll
    for (int i = 0; i < DIM / 32; ++i) {
        float v = row[lane + i * 32];
        s = __fadd_rn(s, __fmul_rn(v, v));
    }
#pragma unroll
    for (int o = 16; o > 0; o >>= 1)
        s = __fadd_rn(s, __shfl_down_sync(0xFFFFFFFFu, s, o));
    return s;
}

__global__ void norms_kernel(const float* __restrict__ z, const float* __restrict__ cb) {
    int gtid = blockIdx.x * blockDim.x + threadIdx.x;
    int warp = gtid >> 5;
    int lane = threadIdx.x & 31;
    if (gtid == 0) { g_loss = 0.0; g_nflag = 0; }
    if (gtid < KCB * DIM / 8) {
        const float4* p = (const float4*)&cb[(size_t)gtid * 8];
        float4 a = p[0], b = p[1];
        __nv_bfloat162 h0 = __floats2bfloat162_rn(a.x, a.y), h1 = __floats2bfloat162_rn(a.z, a.w);
        __nv_bfloat162 h2 = __floats2bfloat162_rn(b.x, b.y), h3 = __floats2bfloat162_rn(b.z, b.w);
        uint4 u;
        u.x = *(uint32_t*)&h0; u.y = *(uint32_t*)&h1;
        u.z = *(uint32_t*)&h2; u.w = *(uint32_t*)&h3;
        *(uint4*)&g_cbh[(size_t)gtid * 8] = u;
    }
    if (warp < N_ROWS) {
        float s = row_sumsq_warp(z + (size_t)warp * DIM, lane);
        if (lane == 0) g_zn[warp] = s;
    }
    if (warp < KCB) {
        float s = row_sumsq_warp(cb + (size_t)warp * DIM, lane);
        if (lane == 0) g_cnorm[warp] = s;
    }
}

// ---------------------------------------------------------------------------
// Screening: raw mma.sync.m16n8k16 bf16->fp32, register-only epilogue.
// CTA = 128 threads (4 warps), 128 rows/CTA (warp owns 32 = 2 m-tiles).
// 16 chunks x 64 codes (8 n-tiles). Lane tracks top-2 for 4 row-slots.
// B tile is code-major in smem, so B fragments come from PLAIN ldmatrix.x2
// (no .trans): lane l ends up holding (n = l>>2, k = 2(l&3)+e) as required.
// ---------------------------------------------------------------------------
#define LDZ 264
#define S_Z   0                        // z bf16 [128][LDZ]   67584 B
#define S_CB  67584                    // cb bf16 [64][LDZ]   33792 B
#define S_CN  101376                   // cnorm f32 [1024]     4096 B
#define S_TOT 105472

#define LDSM_X4(r0, r1, r2, r3, addr) \
    asm volatile("ldmatrix.sync.aligned.m8n8.x4.shared.b16 {%0,%1,%2,%3}, [%4];" \
                 : "=r"(r0), "=r"(r1), "=r"(r2), "=r"(r3) : "r"(addr))
#define LDSM_X2(r0, r1, addr) \
    asm volatile("ldmatrix.sync.aligned.m8n8.x2.shared.b16 {%0,%1}, [%2];" \
                 : "=r"(r0), "=r"(r1) : "r"(addr))
#define MMA16816(c, a, b) \
    asm volatile("mma.sync.aligned.m16n8k16.row.col.f32.bf16.bf16.f32 " \
                 "{%0,%1,%2,%3}, {%4,%5,%6,%7}, {%8,%9}, {%0,%1,%2,%3};" \
                 : "+f"((c)[0]), "+f"((c)[1]), "+f"((c)[2]), "+f"((c)[3]) \
                 : "r"((a)[0]), "r"((a)[1]), "r"((a)[2]), "r"((a)[3]), \
                   "r"((b)[0]), "r"((b)[1]))

__device__ __forceinline__ uint32_t smem_u32(const void* p) {
    uint32_t a;
    asm("{ .reg .u64 t; cvta.to.shared.u64 t, %1; cvt.u32.u64 %0, t; }" : "=r"(a) : "l"(p));
    return a;
}

__global__ void __launch_bounds__(128)
screen_kernel(const float* __restrict__ z) {
    extern __shared__ char smem[];
    __nv_bfloat16* zt  = (__nv_bfloat16*)(smem + S_Z);
    __nv_bfloat16* cbt = (__nv_bfloat16*)(smem + S_CB);
    float* cn_s = (float*)(smem + S_CN);

    const int tid = threadIdx.x, w = tid >> 5, lane = tid & 31;
    const int blockRow = blockIdx.x * 128;
    const int warpRow = w * 32;

    for (int t = tid; t < KCB; t += 128) cn_s[t] = g_cnorm[t];

    // stage z tile [128 x 256] f32 -> bf16
    for (int t = tid; t < 128 * 32; t += 128) {
        int row = t >> 5, c8 = t & 31;
        const float4* p = (const float4*)&z[(size_t)(blockRow + row) * DIM + c8 * 8];
        float4 a = p[0], b = p[1];
        __nv_bfloat162 h0 = __floats2bfloat162_rn(a.x, a.y), h1 = __floats2bfloat162_rn(a.z, a.w);
        __nv_bfloat162 h2 = __floats2bfloat162_rn(b.x, b.y), h3 = __floats2bfloat162_rn(b.z, b.w);
        uint4 u;
        u.x = *(uint32_t*)&h0; u.y = *(uint32_t*)&h1;
        u.z = *(uint32_t*)&h2; u.w = *(uint32_t*)&h3;
        *(uint4*)&zt[row * LDZ + c8 * 8] = u;
    }

    // ldmatrix lane addresses
    const int a_row = (lane & 7) + ((lane >> 3) & 1) * 8;
    const int a_col = ((lane >> 4) & 1) * 8;
    const uint32_t ztb = smem_u32(zt);
    const uint32_t cbb = smem_u32(cbt);
    uint32_t addrA0 = ztb + ((warpRow + a_row) * LDZ + a_col) * 2;
    uint32_t addrA1 = ztb + ((warpRow + 16 + a_row) * LDZ + a_col) * 2;
    const int b_code = (lane & 7);
    const int b_koff = ((lane >> 3) & 1) * 8;

    // 4 row-slots: s = mt*2+hi -> row warpRow + mt*16 + (lane>>2) + hi*8
    float bb[4]  = {3.4e38f, 3.4e38f, 3.4e38f, 3.4e38f};
    float bb2[4] = {3.4e38f, 3.4e38f, 3.4e38f, 3.4e38f};
    int   bi[4]  = {0, 0, 0, 0};

#pragma unroll 1
    for (int c = 0; c < 16; ++c) {
        __syncthreads();
        // stage bf16 codebook chunk [64 x 256]
        for (int t = tid; t < 64 * 32; t += 128) {
            int row = t >> 5, c8 = t & 31;
            uint4 u = *(const uint4*)&g_cbh[(size_t)(c * 64 + row) * DIM + c8 * 8];
            *(uint4*)&cbt[row * LDZ + c8 * 8] = u;
        }
        __syncthreads();

        float acc[2][8][4];
#pragma unroll
        for (int mt = 0; mt < 2; ++mt)
#pragma unroll
            for (int nt = 0; nt < 8; ++nt)
#pragma unroll
                for (int e = 0; e < 4; ++e) acc[mt][nt][e] = 0.f;

#pragma unroll
        for (int ks = 0; ks < 16; ++ks) {
            uint32_t a0[4], a1[4];
            LDSM_X4(a0[0], a0[1], a0[2], a0[3], addrA0 + ks * 32);
            LDSM_X4(a1[0], a1[1], a1[2], a1[3], addrA1 + ks * 32);
            uint32_t bf[8][2];
#pragma unroll
            for (int nt = 0; nt < 8; ++nt) {
                uint32_t ab = cbb + ((nt * 8 + b_code) * LDZ + b_koff + ks * 16) * 2;
                LDSM_X2(bf[nt][0], bf[nt][1], ab);
            }
#pragma unroll
            for (int nt = 0; nt < 8; ++nt) {
                MMA16816(acc[0][nt], a0, bf[nt]);
                MMA16816(acc[1][nt], a1, bf[nt]);
            }
        }

        // register epilogue: k ascending per slot
        const int kq = 2 * (lane & 3);
#pragma unroll
        for (int nt = 0; nt < 8; ++nt) {
            int k0 = c * 64 + nt * 8 + kq;
            float cn0 = cn_s[k0], cn1 = cn_s[k0 + 1];
#pragma unroll
            for (int mt = 0; mt < 2; ++mt) {
#pragma unroll
                for (int hi = 0; hi < 2; ++hi) {
                    int s = mt * 2 + hi;
                    float d0 = acc[mt][nt][hi * 2 + 0];
                    float d1 = acc[mt][nt][hi * 2 + 1];
                    float v0 = fmaf(-2.f, d0, cn0);
                    float v1 = fmaf(-2.f, d1, cn1);
                    if (v0 < bb[s]) { bb2[s] = bb[s]; bb[s] = v0; bi[s] = k0; }
                    else if (v0 < bb2[s]) bb2[s] = v0;
                    if (v1 < bb[s]) { bb2[s] = bb[s]; bb[s] = v1; bi[s] = k0 + 1; }
                    else if (v1 < bb2[s]) bb2[s] = v1;
                }
            }
        }
    }

    // quad merge (lanes 4r..4r+3 share the same row pair)
#pragma unroll
    for (int off = 1; off <= 2; off <<= 1) {
#pragma unroll
        for (int s = 0; s < 4; ++s) {
            float ov  = __shfl_xor_sync(0xFFFFFFFFu, bb[s],  off);
            float ov2 = __shfl_xor_sync(0xFFFFFFFFu, bb2[s], off);
            int   oi  = __shfl_xor_sync(0xFFFFFFFFu, bi[s],  off);
            if (ov < bb[s] || (ov == bb[s] && oi < bi[s])) {
                bb2[s] = fminf(bb[s], ov2);
                bb[s] = ov; bi[s] = oi;
            } else {
                bb2[s] = fminf(bb2[s], ov);
            }
        }
    }

    if ((lane & 3) == 0) {
#pragma unroll
        for (int s = 0; s < 4; ++s) {
            int row = blockRow + warpRow + (s >> 1) * 16 + (lane >> 2) + (s & 1) * 8;
            g_ids[row] = bi[s];
            if (bb2[s] - bb[s] < DELTA) {
                int p = atomicAdd(&g_nflag, 1);
                g_flagged[p] = row;
            }
        }
    }
}

// ---------------------------------------------------------------------------
// Exact rescue (bit-exact FFMA2), BM=32 rows/block
// ---------------------------------------------------------------------------
__global__ void __launch_bounds__(256)
rescue_kernel(const float* __restrict__ z, const float* __restrict__ cb) {
    __shared__ __align__(16) float zs[BD][BM + PAD];
    __shared__ __align__(16) float cs[BD][BN + PAD];
    __shared__ float zn_s[BM];
    __shared__ int   ridx_s[BM];
    __shared__ float redv[BM][16];
    __shared__ int   redi[BM][16];

    const int nf = g_nflag;
    const int blockRow = blockIdx.x * BM;
    if (blockRow >= nf) return;

    const int tid = threadIdx.x;
    const int tx = tid & 15;
    const int ty = tid >> 4;

    if (tid < BM) {
        int s = blockRow + tid;
        int r = g_flagged[(s < nf) ? s : blockRow];
        ridx_s[tid] = r;
        zn_s[tid] = g_zn[r];
    }

    float bestv[2] = {3.4e38f, 3.4e38f};
    int   besti[2] = {0, 0};

    const int c4 = tid & 7;
    const int r0 = tid >> 3;

#pragma unroll 1
    for (int kt = 0; kt < KCB; kt += BN) {
        u64 acc[8];
#pragma unroll
        for (int j = 0; j < 8; ++j) acc[j] = 0ull;

#pragma unroll 1
        for (int dt = 0; dt < DIM; dt += BD) {
            __syncthreads();
            if (r0 < 32) {
                float4 v = *(const float4*)&z[(size_t)ridx_s[r0] * DIM + dt + c4 * 4];
                zs[c4 * 4 + 0][r0] = v.x; zs[c4 * 4 + 1][r0] = v.y;
                zs[c4 * 4 + 2][r0] = v.z; zs[c4 * 4 + 3][r0] = v.w;
            }
#pragma unroll
            for (int q = 0; q < 4; ++q) {
                int r = q * 32 + r0;
                float4 wv = *(const float4*)&cb[(size_t)(kt + r) * DIM + dt + c4 * 4];
                cs[c4 * 4 + 0][r] = wv.x; cs[c4 * 4 + 1][r] = wv.y;
                cs[c4 * 4 + 2][r] = wv.z; cs[c4 * 4 + 3][r] = wv.w;
            }
            __syncthreads();

#pragma unroll 8
            for (int d = 0; d < BD; ++d) {
                u64 zap = *(const u64*)&zs[d][ty * 2];
#pragma unroll
                for (int j = 0; j < 8; ++j) {
                    float cc = cs[d][tx + 16 * j];
                    u64 cd;
                    DUP_F32X2(cd, __float_as_uint(cc));
                    FMA_F32X2(acc[j], zap, cd, acc[j]);
                }
            }
        }

#pragma unroll
        for (int j = 0; j < 8; ++j) {
            int kk = kt + tx + 16 * j;
            float cn = g_cnorm[kk];
            float a0 = lo32(acc[j]), a1 = hi32(acc[j]);
            float s0 = fmaf(-2.f, a0, zn_s[ty * 2 + 0]);
            float v0 = __fadd_rn(s0, cn);
            if (v0 < bestv[0]) { bestv[0] = v0; besti[0] = kk; }
            float s1 = fmaf(-2.f, a1, zn_s[ty * 2 + 1]);
            float v1 = __fadd_rn(s1, cn);
            if (v1 < bestv[1]) { bestv[1] = v1; besti[1] = kk; }
        }
    }

    __syncthreads();
#pragma unroll
    for (int i = 0; i < 2; ++i) {
        redv[ty * 2 + i][tx] = bestv[i];
        redi[ty * 2 + i][tx] = besti[i];
    }
    __syncthreads();
    if (tid < BM && blockRow + tid < nf) {
        float bv = redv[tid][0];
        int   bi = redi[tid][0];
#pragma unroll
        for (int t = 1; t < 16; ++t) {
            float v = redv[tid][t];
            int   ii = redi[tid][t];
            if (v < bv || (v == bv && ii < bi)) { bv = v; bi = ii; }
        }
        g_ids[ridx_s[tid]] = bi;
    }
}

// ---------------------------------------------------------------------------
// Outputs: z | z_q_st = z + (z_q - z) | ids | loss
// ---------------------------------------------------------------------------
__global__ void output_kernel(const float* __restrict__ z,
                              const float* __restrict__ cb,
                              float* __restrict__ out) {
    const size_t ND = (size_t)N_ROWS * DIM;
    int gtid = blockIdx.x * blockDim.x + threadIdx.x;
    size_t base = (size_t)gtid * 4;

    float local = 0.f;
    if (base < ND) {
        int n = (int)(base / DIM);
        int d = (int)(base % DIM);
        float4 zv = *(const float4*)&z[base];
        int id = g_ids[n];
        float4 cv = *(const float4*)&cb[(size_t)id * DIM + d];
        *(float4*)&out[base] = zv;
        float tx_ = __fadd_rn(cv.x, -zv.x), ty_ = __fadd_rn(cv.y, -zv.y);
        float tz_ = __fadd_rn(cv.z, -zv.z), tw_ = __fadd_rn(cv.w, -zv.w);
        float4 st;
        st.x = __fadd_rn(zv.x, tx_); st.y = __fadd_rn(zv.y, ty_);
        st.z = __fadd_rn(zv.z, tz_); st.w = __fadd_rn(zv.w, tw_);
        *(float4*)&out[ND + base] = st;
        local = tx_ * tx_ + ty_ * ty_ + tz_ * tz_ + tw_ * tw_;
    }
    if (gtid < N_ROWS) out[2 * ND + gtid] = (float)g_ids[gtid];

    __shared__ float warp_s[8];
#pragma unroll
    for (int o = 16; o > 0; o >>= 1)
        local += __shfl_down_sync(0xFFFFFFFFu, local, o);
    if ((threadIdx.x & 31) == 0) warp_s[threadIdx.x >> 5] = local;
    __syncthreads();
    if (threadIdx.x < 8) {
        float v = warp_s[threadIdx.x];
#pragma unroll
        for (int o = 4; o > 0; o >>= 1)
            v += __shfl_down_sync(0xFFu, v, o);
        if (threadIdx.x == 0 && v != 0.f) atomicAdd(&g_loss, (double)v);
    }
}

__global__ void finalize_kernel(float* __restrict__ out) {
    const size_t ND = (size_t)N_ROWS * DIM;
    out[2 * ND + N_ROWS] = (float)(1.25 * g_loss / (double)ND);
}

// ---------------------------------------------------------------------------
extern "C" void kernel_launch(void* const* d_in, const int* in_sizes, int n_in,
                              void* d_out, int out_size) {
    const float* z  = (const float*)d_in[0];
    const float* cb = (const float*)d_in[1];
    float* out = (float*)d_out;

    cudaFuncSetAttribute(screen_kernel, cudaFuncAttributeMaxDynamicSharedMemorySize, S_TOT);

    norms_kernel<<<(N_ROWS * 32 + 255) / 256, 256>>>(z, cb);
    screen_kernel<<<N_ROWS / 128, 128, S_TOT>>>(z);
    rescue_kernel<<<N_ROWS / BM, 256>>>(z, cb);
    const size_t ND = (size_t)N_ROWS * DIM;
    int nblk = (int)((ND / 4 + 255) / 256);
    output_kernel<<<nblk, 256>>>(z, cb, out);
    finalize_kernel<<<1, 1>>>(out);
}

// round 12
// speedup vs baseline: 1.5663x; 1.0192x over previous
#include <cuda_runtime.h>
#include <cuda_bf16.h>
#include <cstdint>

#define N_ROWS 131072
#define DIM    256
#define KCB    1024
#define DELTA  1.0e-3f

// rescue tile
#define BM 32
#define BN 128
#define BD 32
#define PAD 4

__device__ float  g_cnorm[KCB];
__device__ float  g_zn[N_ROWS];
__device__ int    g_ids[N_ROWS];
__device__ int    g_flagged[N_ROWS];
__device__ int    g_nflag;
__device__ double g_loss;
__device__ __align__(16) __nv_bfloat16 g_cbh[KCB * DIM];

typedef unsigned long long u64;

#define FMA_F32X2(d, a, b, c) \
    asm("fma.rn.f32x2 %0, %1, %2, %3;" : "=l"(d) : "l"(a), "l"(b), "l"(c))
#define DUP_F32X2(d, x) \
    asm("mov.b64 %0, {%1, %1};" : "=l"(d) : "r"(x))
__device__ __forceinline__ float lo32(u64 v) { return __uint_as_float((unsigned)(v & 0xFFFFFFFFu)); }
__device__ __forceinline__ float hi32(u64 v) { return __uint_as_float((unsigned)(v >> 32)); }

// ---------------------------------------------------------------------------
// Bit-exact row norms (XLA order) + codebook bf16 pre-conversion
// ---------------------------------------------------------------------------
__device__ __forceinline__ float row_sumsq_warp(const float* __restrict__ row, int lane) {
    float s = 0.f;
#pragma unroll
    for (int i = 0; i < DIM / 32; ++i) {
        float v = row[lane + i * 32];
        s = __fadd_rn(s, __fmul_rn(v, v));
    }
#pragma unroll
    for (int o = 16; o > 0; o >>= 1)
        s = __fadd_rn(s, __shfl_down_sync(0xFFFFFFFFu, s, o));
    return s;
}

__global__ void norms_kernel(const float* __restrict__ z, const float* __restrict__ cb) {
    int gtid = blockIdx.x * blockDim.x + threadIdx.x;
    int warp = gtid >> 5;
    int lane = threadIdx.x & 31;
    if (gtid == 0) { g_loss = 0.0; g_nflag = 0; }
    if (gtid < KCB * DIM / 8) {
        const float4* p = (const float4*)&cb[(size_t)gtid * 8];
        float4 a = p[0], b = p[1];
        __nv_bfloat162 h0 = __floats2bfloat162_rn(a.x, a.y), h1 = __floats2bfloat162_rn(a.z, a.w);
        __nv_bfloat162 h2 = __floats2bfloat162_rn(b.x, b.y), h3 = __floats2bfloat162_rn(b.z, b.w);
        uint4 u;
        u.x = *(uint32_t*)&h0; u.y = *(uint32_t*)&h1;
        u.z = *(uint32_t*)&h2; u.w = *(uint32_t*)&h3;
        *(uint4*)&g_cbh[(size_t)gtid * 8] = u;
    }
    if (warp < N_ROWS) {
        float s = row_sumsq_warp(z + (size_t)warp * DIM, lane);
        if (lane == 0) g_zn[warp] = s;
    }
    if (warp < KCB) {
        float s = row_sumsq_warp(cb + (size_t)warp * DIM, lane);
        if (lane == 0) g_cnorm[warp] = s;
    }
}

// ---------------------------------------------------------------------------
// Screening: raw mma.sync.m16n8k16 bf16->fp32, register-only epilogue.
// CTA = 256 threads (8 warps), 256 rows/CTA (warp owns 32 = 2 m-tiles).
// Codebook chunks of 64 codes, cp.async DOUBLE-BUFFERED so chunk c+1 streams
// gmem->smem while chunk c computes. Plain ldmatrix.x2 for B (code-major).
// ---------------------------------------------------------------------------
#define LDZ 264
#define S_Z    0                       // z bf16 [256][LDZ]   135168 B
#define S_CB0  135168                  // cb buf0 [64][LDZ]    33792 B
#define S_CB1  168960                  // cb buf1 [64][LDZ]    33792 B
#define S_CN   202752                  // cnorm f32 [1024]      4096 B
#define S_TOT  206848

#define LDSM_X4(r0, r1, r2, r3, addr) \
    asm volatile("ldmatrix.sync.aligned.m8n8.x4.shared.b16 {%0,%1,%2,%3}, [%4];" \
                 : "=r"(r0), "=r"(r1), "=r"(r2), "=r"(r3) : "r"(addr))
#define LDSM_X2(r0, r1, addr) \
    asm volatile("ldmatrix.sync.aligned.m8n8.x2.shared.b16 {%0,%1}, [%2];" \
                 : "=r"(r0), "=r"(r1) : "r"(addr))
#define MMA16816(c, a, b) \
    asm volatile("mma.sync.aligned.m16n8k16.row.col.f32.bf16.bf16.f32 " \
                 "{%0,%1,%2,%3}, {%4,%5,%6,%7}, {%8,%9}, {%0,%1,%2,%3};" \
                 : "+f"((c)[0]), "+f"((c)[1]), "+f"((c)[2]), "+f"((c)[3]) \
                 : "r"((a)[0]), "r"((a)[1]), "r"((a)[2]), "r"((a)[3]), \
                   "r"((b)[0]), "r"((b)[1]))
#define CP_ASYNC16(smem_addr, gptr) \
    asm volatile("cp.async.cg.shared.global [%0], [%1], 16;" \
                 :: "r"(smem_addr), "l"(gptr) : "memory")
#define CP_COMMIT() asm volatile("cp.async.commit_group;" ::: "memory")

__device__ __forceinline__ uint32_t smem_u32(const void* p) {
    uint32_t a;
    asm("{ .reg .u64 t; cvta.to.shared.u64 t, %1; cvt.u32.u64 %0, t; }" : "=r"(a) : "l"(p));
    return a;
}

__global__ void __launch_bounds__(256)
screen_kernel(const float* __restrict__ z) {
    extern __shared__ char smem[];
    __nv_bfloat16* zt = (__nv_bfloat16*)(smem + S_Z);
    float* cn_s = (float*)(smem + S_CN);

    const int tid = threadIdx.x, w = tid >> 5, lane = tid & 31;
    const int blockRow = blockIdx.x * 256;
    const int warpRow = w * 32;

    const uint32_t sb = smem_u32(smem);
    const uint32_t cbBuf[2] = {sb + S_CB0, sb + S_CB1};

    for (int t = tid; t < KCB; t += 256) cn_s[t] = g_cnorm[t];

    // stage z tile [256 x 256] f32 -> bf16
    for (int t = tid; t < 256 * 32; t += 256) {
        int row = t >> 5, c8 = t & 31;
        const float4* p = (const float4*)&z[(size_t)(blockRow + row) * DIM + c8 * 8];
        float4 a = p[0], b = p[1];
        __nv_bfloat162 h0 = __floats2bfloat162_rn(a.x, a.y), h1 = __floats2bfloat162_rn(a.z, a.w);
        __nv_bfloat162 h2 = __floats2bfloat162_rn(b.x, b.y), h3 = __floats2bfloat162_rn(b.z, b.w);
        uint4 u;
        u.x = *(uint32_t*)&h0; u.y = *(uint32_t*)&h1;
        u.z = *(uint32_t*)&h2; u.w = *(uint32_t*)&h3;
        *(uint4*)&zt[row * LDZ + c8 * 8] = u;
    }

    // cp.async staging of a 64-code chunk (32KB): 2048 x 16B, 8 per thread
    auto stage = [&](int c, uint32_t buf) {
#pragma unroll
        for (int i = 0; i < 8; ++i) {
            int idx = tid + i * 256;         // 0..2047
            int row = idx >> 5;              // 0..63
            int c16 = idx & 31;              // 16B unit within row
            const __nv_bfloat16* src = &g_cbh[(size_t)(c * 64 + row) * DIM + c16 * 8];
            uint32_t dst = buf + (uint32_t)(row * LDZ + c16 * 8) * 2;
            CP_ASYNC16(dst, src);
        }
        CP_COMMIT();
    };

    // ldmatrix lane addresses
    const int a_row = (lane & 7) + ((lane >> 3) & 1) * 8;
    const int a_col = ((lane >> 4) & 1) * 8;
    const uint32_t ztb = sb + S_Z;
    uint32_t addrA0 = ztb + ((warpRow + a_row) * LDZ + a_col) * 2;
    uint32_t addrA1 = ztb + ((warpRow + 16 + a_row) * LDZ + a_col) * 2;
    const int b_code = (lane & 7);
    const int b_koff = ((lane >> 3) & 1) * 8;

    float bb[4]  = {3.4e38f, 3.4e38f, 3.4e38f, 3.4e38f};
    float bb2[4] = {3.4e38f, 3.4e38f, 3.4e38f, 3.4e38f};
    int   bi[4]  = {0, 0, 0, 0};

    stage(0, cbBuf[0]);

#pragma unroll 1
    for (int c = 0; c < 16; ++c) {
        if (c < 15) stage(c + 1, cbBuf[(c + 1) & 1]);
        if (c < 15) { asm volatile("cp.async.wait_group 1;" ::: "memory"); }
        else        { asm volatile("cp.async.wait_group 0;" ::: "memory"); }
        __syncthreads();
        const uint32_t cbb = cbBuf[c & 1];

        float acc[2][8][4];
#pragma unroll
        for (int mt = 0; mt < 2; ++mt)
#pragma unroll
            for (int nt = 0; nt < 8; ++nt)
#pragma unroll
                for (int e = 0; e < 4; ++e) acc[mt][nt][e] = 0.f;

#pragma unroll
        for (int ks = 0; ks < 16; ++ks) {
            uint32_t a0[4], a1[4];
            LDSM_X4(a0[0], a0[1], a0[2], a0[3], addrA0 + ks * 32);
            LDSM_X4(a1[0], a1[1], a1[2], a1[3], addrA1 + ks * 32);
            uint32_t bf[8][2];
#pragma unroll
            for (int nt = 0; nt < 8; ++nt) {
                uint32_t ab = cbb + ((nt * 8 + b_code) * LDZ + b_koff + ks * 16) * 2;
                LDSM_X2(bf[nt][0], bf[nt][1], ab);
            }
#pragma unroll
            for (int nt = 0; nt < 8; ++nt) {
                MMA16816(acc[0][nt], a0, bf[nt]);
                MMA16816(acc[1][nt], a1, bf[nt]);
            }
        }

        // register epilogue: k ascending per slot
        const int kq = 2 * (lane & 3);
#pragma unroll
        for (int nt = 0; nt < 8; ++nt) {
            int k0 = c * 64 + nt * 8 + kq;
            float cn0 = cn_s[k0], cn1 = cn_s[k0 + 1];
#pragma unroll
            for (int mt = 0; mt < 2; ++mt) {
#pragma unroll
                for (int hi = 0; hi < 2; ++hi) {
                    int s = mt * 2 + hi;
                    float d0 = acc[mt][nt][hi * 2 + 0];
                    float d1 = acc[mt][nt][hi * 2 + 1];
                    float v0 = fmaf(-2.f, d0, cn0);
                    float v1 = fmaf(-2.f, d1, cn1);
                    if (v0 < bb[s]) { bb2[s] = bb[s]; bb[s] = v0; bi[s] = k0; }
                    else if (v0 < bb2[s]) bb2[s] = v0;
                    if (v1 < bb[s]) { bb2[s] = bb[s]; bb[s] = v1; bi[s] = k0 + 1; }
                    else if (v1 < bb2[s]) bb2[s] = v1;
                }
            }
        }
        __syncthreads();   // all warps done reading this buffer before restage
    }

    // quad merge (lanes 4r..4r+3 share the same row pair)
#pragma unroll
    for (int off = 1; off <= 2; off <<= 1) {
#pragma unroll
        for (int s = 0; s < 4; ++s) {
            float ov  = __shfl_xor_sync(0xFFFFFFFFu, bb[s],  off);
            float ov2 = __shfl_xor_sync(0xFFFFFFFFu, bb2[s], off);
            int   oi  = __shfl_xor_sync(0xFFFFFFFFu, bi[s],  off);
            if (ov < bb[s] || (ov == bb[s] && oi < bi[s])) {
                bb2[s] = fminf(bb[s], ov2);
                bb[s] = ov; bi[s] = oi;
            } else {
                bb2[s] = fminf(bb2[s], ov);
            }
        }
    }

    if ((lane & 3) == 0) {
#pragma unroll
        for (int s = 0; s < 4; ++s) {
            int row = blockRow + warpRow + (s >> 1) * 16 + (lane >> 2) + (s & 1) * 8;
            g_ids[row] = bi[s];
            if (bb2[s] - bb[s] < DELTA) {
                int p = atomicAdd(&g_nflag, 1);
                g_flagged[p] = row;
            }
        }
    }
}

// ---------------------------------------------------------------------------
// Exact rescue (bit-exact FFMA2), BM=32 rows/block
// ---------------------------------------------------------------------------
__global__ void __launch_bounds__(256)
rescue_kernel(const float* __restrict__ z, const float* __restrict__ cb) {
    __shared__ __align__(16) float zs[BD][BM + PAD];
    __shared__ __align__(16) float cs[BD][BN + PAD];
    __shared__ float zn_s[BM];
    __shared__ int   ridx_s[BM];
    __shared__ float redv[BM][16];
    __shared__ int   redi[BM][16];

    const int nf = g_nflag;
    const int blockRow = blockIdx.x * BM;
    if (blockRow >= nf) return;

    const int tid = threadIdx.x;
    const int tx = tid & 15;
    const int ty = tid >> 4;

    if (tid < BM) {
        int s = blockRow + tid;
        int r = g_flagged[(s < nf) ? s : blockRow];
        ridx_s[tid] = r;
        zn_s[tid] = g_zn[r];
    }

    float bestv[2] = {3.4e38f, 3.4e38f};
    int   besti[2] = {0, 0};

    const int c4 = tid & 7;
    const int r0 = tid >> 3;

#pragma unroll 1
    for (int kt = 0; kt < KCB; kt += BN) {
        u64 acc[8];
#pragma unroll
        for (int j = 0; j < 8; ++j) acc[j] = 0ull;

#pragma unroll 1
        for (int dt = 0; dt < DIM; dt += BD) {
            __syncthreads();
            if (r0 < 32) {
                float4 v = *(const float4*)&z[(size_t)ridx_s[r0] * DIM + dt + c4 * 4];
                zs[c4 * 4 + 0][r0] = v.x; zs[c4 * 4 + 1][r0] = v.y;
                zs[c4 * 4 + 2][r0] = v.z; zs[c4 * 4 + 3][r0] = v.w;
            }
#pragma unroll
            for (int q = 0; q < 4; ++q) {
                int r = q * 32 + r0;
                float4 wv = *(const float4*)&cb[(size_t)(kt + r) * DIM + dt + c4 * 4];
                cs[c4 * 4 + 0][r] = wv.x; cs[c4 * 4 + 1][r] = wv.y;
                cs[c4 * 4 + 2][r] = wv.z; cs[c4 * 4 + 3][r] = wv.w;
            }
            __syncthreads();

#pragma unroll 8
            for (int d = 0; d < BD; ++d) {
                u64 zap = *(const u64*)&zs[d][ty * 2];
#pragma unroll
                for (int j = 0; j < 8; ++j) {
                    float cc = cs[d][tx + 16 * j];
                    u64 cd;
                    DUP_F32X2(cd, __float_as_uint(cc));
                    FMA_F32X2(acc[j], zap, cd, acc[j]);
                }
            }
        }

#pragma unroll
        for (int j = 0; j < 8; ++j) {
            int kk = kt + tx + 16 * j;
            float cn = g_cnorm[kk];
            float a0 = lo32(acc[j]), a1 = hi32(acc[j]);
            float s0 = fmaf(-2.f, a0, zn_s[ty * 2 + 0]);
            float v0 = __fadd_rn(s0, cn);
            if (v0 < bestv[0]) { bestv[0] = v0; besti[0] = kk; }
            float s1 = fmaf(-2.f, a1, zn_s[ty * 2 + 1]);
            float v1 = __fadd_rn(s1, cn);
            if (v1 < bestv[1]) { bestv[1] = v1; besti[1] = kk; }
        }
    }

    __syncthreads();
#pragma unroll
    for (int i = 0; i < 2; ++i) {
        redv[ty * 2 + i][tx] = bestv[i];
        redi[ty * 2 + i][tx] = besti[i];
    }
    __syncthreads();
    if (tid < BM && blockRow + tid < nf) {
        float bv = redv[tid][0];
        int   bi = redi[tid][0];
#pragma unroll
        for (int t = 1; t < 16; ++t) {
            float v = redv[tid][t];
            int   ii = redi[tid][t];
            if (v < bv || (v == bv && ii < bi)) { bv = v; bi = ii; }
        }
        g_ids[ridx_s[tid]] = bi;
    }
}

// ---------------------------------------------------------------------------
// Outputs: z | z_q_st = z + (z_q - z) | ids | loss
// ---------------------------------------------------------------------------
__global__ void output_kernel(const float* __restrict__ z,
                              const float* __restrict__ cb,
                              float* __restrict__ out) {
    const size_t ND = (size_t)N_ROWS * DIM;
    int gtid = blockIdx.x * blockDim.x + threadIdx.x;
    size_t base = (size_t)gtid * 4;

    float local = 0.f;
    if (base < ND) {
        int n = (int)(base / DIM);
        int d = (int)(base % DIM);
        float4 zv = *(const float4*)&z[base];
        int id = g_ids[n];
        float4 cv = *(const float4*)&cb[(size_t)id * DIM + d];
        *(float4*)&out[base] = zv;
        float tx_ = __fadd_rn(cv.x, -zv.x), ty_ = __fadd_rn(cv.y, -zv.y);
        float tz_ = __fadd_rn(cv.z, -zv.z), tw_ = __fadd_rn(cv.w, -zv.w);
        float4 st;
        st.x = __fadd_rn(zv.x, tx_); st.y = __fadd_rn(zv.y, ty_);
        st.z = __fadd_rn(zv.z, tz_); st.w = __fadd_rn(zv.w, tw_);
        *(float4*)&out[ND + base] = st;
        local = tx_ * tx_ + ty_ * ty_ + tz_ * tz_ + tw_ * tw_;
    }
    if (gtid < N_ROWS) out[2 * ND + gtid] = (float)g_ids[gtid];

    __shared__ float warp_s[8];
#pragma unroll
    for (int o = 16; o > 0; o >>= 1)
        local += __shfl_down_sync(0xFFFFFFFFu, local, o);
    if ((threadIdx.x & 31) == 0) warp_s[threadIdx.x >> 5] = local;
    __syncthreads();
    if (threadIdx.x < 8) {
        float v = warp_s[threadIdx.x];
#pragma unroll
        for (int o = 4; o > 0; o >>= 1)
            v += __shfl_down_sync(0xFFu, v, o);
        if (threadIdx.x == 0 && v != 0.f) atomicAdd(&g_loss, (double)v);
    }
}

__global__ void finalize_kernel(float* __restrict__ out) {
    const size_t ND = (size_t)N_ROWS * DIM;
    out[2 * ND + N_ROWS] = (float)(1.25 * g_loss / (double)ND);
}

// ---------------------------------------------------------------------------
extern "C" void kernel_launch(void* const* d_in, const int* in_sizes, int n_in,
                              void* d_out, int out_size) {
    const float* z  = (const float*)d_in[0];
    const float* cb = (const float*)d_in[1];
    float* out = (float*)d_out;

    cudaFuncSetAttribute(screen_kernel, cudaFuncAttributeMaxDynamicSharedMemorySize, S_TOT);

    norms_kernel<<<(N_ROWS * 32 + 255) / 256, 256>>>(z, cb);
    screen_kernel<<<N_ROWS / 256, 256, S_TOT>>>(z);
    rescue_kernel<<<N_ROWS / BM, 256>>>(z, cb);
    const size_t ND = (size_t)N_ROWS * DIM;
    int nblk = (int)((ND / 4 + 255) / 256);
    output_kernel<<<nblk, 256>>>(z, cb, out);
    finalize_kernel<<<1, 1>>>(out);
}